// round 6
// baseline (speedup 1.0000x reference)
#include <cuda_runtime.h>
#include <math_constants.h>

#define S_TOTAL 4096
#define BATCH   64
#define DIM     256
#define CHUNKS  32
#define CHUNK_S 128   // S_TOTAL / CHUNKS
#define SUB_S   32    // subtile rows staged in SMEM

// Scratch (allocation-free rule: __device__ globals)
__device__ float g_key[BATCH * DIM];
__device__ float g_m[BATCH * CHUNKS];
__device__ float g_l[BATCH * CHUNKS];
__device__ float g_acc[BATCH * CHUNKS * DIM];
__device__ int   g_len_is64;   // 1 if sequence_lengths is int64, 0 if int32

// ---------------------------------------------------------------------------
// Kernel 0: detect sequence_lengths dtype.
// View buffer as int32 words. Lengths are all >= 1, so:
//   int64 layout: words 1,3,...,63 (high halves of lens[0..31]) are ALL zero.
//   int32 layout: words 1,3,...,63 are lens[1..63], ALL nonzero.
// Words [0,64) are in-bounds for both layouts (int32: exactly 64 words).
// ---------------------------------------------------------------------------
__global__ void detect_kernel(const int* __restrict__ lens_w) {
    int any_odd_nonzero = 0;
#pragma unroll
    for (int i = 1; i < 64; i += 2)
        any_odd_nonzero |= (lens_w[i] != 0);
    g_len_is64 = any_odd_nonzero ? 0 : 1;
}

__device__ __forceinline__ int load_len(const void* lens, int b) {
    if (g_len_is64)
        return (int)((const long long*)lens)[b];
    return ((const int*)lens)[b];
}

// ---------------------------------------------------------------------------
// Kernel 1: key[b][d] = bias[d] + sum_j query[b][j] * W[d][j]
// ---------------------------------------------------------------------------
__global__ void key_kernel(const float* __restrict__ q,
                           const float* __restrict__ W,
                           const float* __restrict__ bias) {
    const int b = blockIdx.x;
    const int t = threadIdx.x;
    __shared__ float qs[DIM];
    qs[t] = q[b * DIM + t];
    __syncthreads();
    const float4* W4 = reinterpret_cast<const float4*>(W + t * DIM);
    const float4* q4 = reinterpret_cast<const float4*>(qs);
    float acc = bias[t];
#pragma unroll 8
    for (int j = 0; j < DIM / 4; j++) {
        float4 w = W4[j];
        float4 qq = q4[j];
        acc += w.x * qq.x + w.y * qq.y + w.z * qq.z + w.w * qq.w;
    }
    g_key[b * DIM + t] = acc;
}

// ---------------------------------------------------------------------------
// Kernel 2: flash-style partial softmax-attention over one (batch, chunk).
// Each block: b = blockIdx.y, chunk c = blockIdx.x covering s in
// [c*CHUNK_S, c*CHUNK_S + CHUNK_S), clipped by sequence length.
// Produces unnormalized partial (m, l, acc[DIM]) per chunk.
// ---------------------------------------------------------------------------
__global__ void flash_kernel(const float* __restrict__ attended,
                             const void* __restrict__ lens) {
    const int c   = blockIdx.x;
    const int b   = blockIdx.y;
    const int tid = threadIdx.x;
    const int len = load_len(lens, b);
    const int sbeg = c * CHUNK_S;
    const int idx  = b * CHUNKS + c;

    if (len <= sbeg) {
        // Entire chunk masked: mark invalid; reducer skips l==0 chunks.
        if (tid == 0) g_l[idx] = 0.f;
        return;
    }

    __shared__ float tile[SUB_S * DIM];   // 32 KB
    __shared__ float keys[DIM];
    __shared__ float sc[SUB_S];
    __shared__ float sp[SUB_S];

    keys[tid] = g_key[b * DIM + tid];

    const int send = min(sbeg + CHUNK_S, len);
    const int lane = tid & 31;
    const int wrp  = tid >> 5;

    float m = -CUDART_INF_F;
    float l = 0.f;
    float acc = 0.f;

    for (int s0 = sbeg; s0 < send; s0 += SUB_S) {
        const int nv = min(SUB_S, send - s0);

        __syncthreads();  // protect tile/sc/sp from previous iteration readers

        // --- stage nv rows of attended[s, b, :] into SMEM (float4, coalesced)
        const float4* src = reinterpret_cast<const float4*>(
            attended + (size_t)s0 * BATCH * DIM + (size_t)b * DIM);
        for (int i = tid; i < nv * (DIM / 4); i += DIM) {
            int r  = i >> 6;       // / (DIM/4)
            int c4 = i & 63;
            reinterpret_cast<float4*>(tile)[r * (DIM / 4) + c4] =
                src[(size_t)r * (BATCH * DIM / 4) + c4];
        }
        __syncthreads();

        // --- scores: warp w handles s = w, w+8, ... ; stride-32 lane access
        // (conflict-free scalar LDS), warp-shuffle reduce.
        for (int s = wrp; s < nv; s += 8) {
            const float* trow = tile + s * DIM;
            float p = 0.f;
#pragma unroll
            for (int k = 0; k < 8; k++)
                p += trow[lane + 32 * k] * keys[lane + 32 * k];
#pragma unroll
            for (int off = 16; off; off >>= 1)
                p += __shfl_xor_sync(0xffffffffu, p, off);
            if (lane == 0) sc[s] = p;
        }
        __syncthreads();

        // --- online softmax update
        float tmax = -CUDART_INF_F;
        for (int s = 0; s < nv; s++) tmax = fmaxf(tmax, sc[s]);
        const float m_new = fmaxf(m, tmax);
        const float scale = __expf(m - m_new);   // exp(-inf)=0 on first tile

        if (wrp == 0)   // compute p once (avoid 256x-redundant MUFU work)
            sp[lane] = (lane < nv) ? __expf(sc[lane] - m_new) : 0.f;

        acc *= scale;
        l   *= scale;
        m    = m_new;
        __syncthreads();

        float lsum = 0.f;
        for (int s = 0; s < nv; s++) {
            const float pv = sp[s];           // broadcast LDS
            lsum += pv;
            acc  += pv * tile[s * DIM + tid]; // conflict-free LDS
        }
        l += lsum;
    }

    if (tid == 0) { g_m[idx] = m; g_l[idx] = l; }
    g_acc[(size_t)idx * DIM + tid] = acc;
}

// ---------------------------------------------------------------------------
// Kernel 3: merge CHUNKS partials per batch row, normalize, write output.
// ---------------------------------------------------------------------------
__global__ void reduce_kernel(float* __restrict__ out) {
    const int b   = blockIdx.x;
    const int tid = threadIdx.x;

    float M = -CUDART_INF_F;
    for (int ci = 0; ci < CHUNKS; ci++)
        if (g_l[b * CHUNKS + ci] > 0.f)
            M = fmaxf(M, g_m[b * CHUNKS + ci]);

    float L = 0.f, a = 0.f;
    for (int ci = 0; ci < CHUNKS; ci++) {
        const float lc = g_l[b * CHUNKS + ci];
        if (lc > 0.f) {
            const float wgt = __expf(g_m[b * CHUNKS + ci] - M);
            L += lc * wgt;
            a += wgt * g_acc[(size_t)(b * CHUNKS + ci) * DIM + tid];
        }
    }
    out[b * DIM + tid] = a / L;
}

// ---------------------------------------------------------------------------
// Launch. Inputs identified by element count (robust to metadata ordering):
//   query 16384 f32, attended 67108864 f32, sequence_lengths 64 (i32 or i64),
//   W 65536 f32, b 256 f32. Output: [B, D] f32.
// ---------------------------------------------------------------------------
extern "C" void kernel_launch(void* const* d_in, const int* in_sizes, int n_in,
                              void* d_out, int out_size) {
    const float* q = nullptr;
    const float* att = nullptr;
    const void*  lens = nullptr;
    const float* W = nullptr;
    const float* bias = nullptr;

    for (int i = 0; i < n_in; i++) {
        switch (in_sizes[i]) {
            case BATCH * DIM:                 q    = (const float*)d_in[i]; break;
            case S_TOTAL * BATCH * DIM:       att  = (const float*)d_in[i]; break;
            case BATCH:                       lens = d_in[i];               break;
            case DIM * DIM:                   W    = (const float*)d_in[i]; break;
            case DIM:                         bias = (const float*)d_in[i]; break;
            default: break;
        }
    }

    float* out = (float*)d_out;

    detect_kernel<<<1, 1>>>((const int*)lens);
    key_kernel<<<BATCH, DIM>>>(q, W, bias);
    dim3 grid(CHUNKS, BATCH);
    flash_kernel<<<grid, DIM>>>(att, lens);
    reduce_kernel<<<BATCH, DIM>>>(out);
}

// round 8
// speedup vs baseline: 1.2397x; 1.2397x over previous
#include <cuda_runtime.h>
#include <cuda_pipeline.h>
#include <math_constants.h>

#define S_TOTAL 4096
#define BATCH   64
#define DIM     256
#define CHUNKS  32
#define CHUNK_S 128   // S_TOTAL / CHUNKS
#define SUB_S   32    // subtile rows staged per pipeline stage

// Scratch (allocation-free rule: __device__ globals; zero-initialized at load,
// masked chunks' g_acc/g_m/g_l slots are never written -> stay finite 0).
__device__ float g_key[BATCH * DIM];
__device__ float g_m[BATCH * CHUNKS];
__device__ float g_l[BATCH * CHUNKS];
__device__ float g_acc[BATCH * CHUNKS * DIM];
__device__ int   g_len_is64;   // 1 if sequence_lengths is int64, 0 if int32

__device__ __forceinline__ int load_len(const void* lens, int b) {
    if (g_len_is64)
        return (int)((const long long*)lens)[b];
    return ((const int*)lens)[b];
}

// ---------------------------------------------------------------------------
// Kernel 1: key[b][d] = bias[d] + sum_j query[b][j] * W[d][j]
// Block 0 / thread 0 also detects the sequence_lengths dtype:
// lengths are all >= 1, so viewing the buffer as int32 words, the odd words
// are ALL zero iff the layout is int64 (high halves). flash_kernel launches
// after this kernel completes, so the flag write is ordered.
// ---------------------------------------------------------------------------
__global__ __launch_bounds__(DIM)
void key_kernel(const float* __restrict__ q,
                const float* __restrict__ W,
                const float* __restrict__ bias,
                const int*   __restrict__ lens_w) {
    const int b = blockIdx.x;
    const int t = threadIdx.x;
    if (b == 0 && t == 0) {
        int any_odd_nonzero = 0;
#pragma unroll
        for (int i = 1; i < 64; i += 2)
            any_odd_nonzero |= (lens_w[i] != 0);
        g_len_is64 = any_odd_nonzero ? 0 : 1;
    }
    __shared__ float qs[DIM];
    qs[t] = q[b * DIM + t];
    __syncthreads();
    const float4* W4 = reinterpret_cast<const float4*>(W + t * DIM);
    const float4* q4 = reinterpret_cast<const float4*>(qs);
    float acc = bias[t];
#pragma unroll 8
    for (int j = 0; j < DIM / 4; j++) {
        float4 w = W4[j];
        float4 qq = q4[j];
        acc += w.x * qq.x + w.y * qq.y + w.z * qq.z + w.w * qq.w;
    }
    g_key[b * DIM + t] = acc;
}

// ---------------------------------------------------------------------------
// Kernel 2: flash-style partial softmax-attention over one (batch, chunk),
// with a 2-stage cp.async pipeline staging 32-row subtiles so DRAM latency
// overlaps compute within the CTA.
// Dynamic SMEM layout: tile[2][SUB_S*DIM] | keys[DIM] | sc[SUB_S] | sp[SUB_S]
// ---------------------------------------------------------------------------
__global__ __launch_bounds__(DIM)
void flash_kernel(const float* __restrict__ attended,
                  const void* __restrict__ lens) {
    const int c   = blockIdx.x;
    const int b   = blockIdx.y;
    const int tid = threadIdx.x;
    const int len = load_len(lens, b);
    const int sbeg = c * CHUNK_S;
    const int idx  = b * CHUNKS + c;

    if (len <= sbeg) {
        if (tid == 0) g_l[idx] = 0.f;   // mark invalid; reducer gives it weight 0
        return;
    }

    extern __shared__ float smem[];
    float* tile = smem;                           // 2 * SUB_S * DIM floats
    float* keys = smem + 2 * SUB_S * DIM;         // DIM
    float* sc   = keys + DIM;                     // SUB_S
    float* sp   = sc + SUB_S;                     // SUB_S

    keys[tid] = g_key[b * DIM + tid];

    const int send = min(sbeg + CHUNK_S, len);
    const int nsub = (send - sbeg + SUB_S - 1) / SUB_S;
    const int lane = tid & 31;
    const int wrp  = tid >> 5;

    const float4* src_base = reinterpret_cast<const float4*>(
        attended + (size_t)b * DIM);

    // issue async stage of subtile t into buffer t&1
    auto issue = [&](int t) {
        const int s0 = sbeg + t * SUB_S;
        const int nv = min(SUB_S, send - s0);
        float4* dst = reinterpret_cast<float4*>(tile + (t & 1) * SUB_S * DIM);
        const float4* src = src_base + (size_t)s0 * (BATCH * DIM / 4);
        for (int i = tid; i < nv * (DIM / 4); i += DIM) {
            int r  = i >> 6;      // / (DIM/4)
            int c4 = i & 63;
            __pipeline_memcpy_async(&dst[r * (DIM / 4) + c4],
                                    &src[(size_t)r * (BATCH * DIM / 4) + c4], 16);
        }
        __pipeline_commit();
    };

    issue(0);

    float m = -CUDART_INF_F;
    float l = 0.f;
    float acc = 0.f;

    for (int t = 0; t < nsub; t++) {
        const int s0 = sbeg + t * SUB_S;
        const int nv = min(SUB_S, send - s0);
        float* buf = tile + (t & 1) * SUB_S * DIM;

        if (t + 1 < nsub) {
            issue(t + 1);
            __pipeline_wait_prior(1);   // group t complete, t+1 in flight
        } else {
            __pipeline_wait_prior(0);
        }
        __syncthreads();                 // staged data visible to all threads

        // --- scores: warp w handles s = w, w+8, ...; stride-32 lane access
        for (int s = wrp; s < nv; s += 8) {
            const float* trow = buf + s * DIM;
            float p = 0.f;
#pragma unroll
            for (int k = 0; k < 8; k++)
                p += trow[lane + 32 * k] * keys[lane + 32 * k];
#pragma unroll
            for (int off = 16; off; off >>= 1)
                p += __shfl_xor_sync(0xffffffffu, p, off);
            if (lane == 0) sc[s] = p;
        }
        __syncthreads();

        // --- online softmax update
        float tmax = -CUDART_INF_F;
        for (int s = 0; s < nv; s++) tmax = fmaxf(tmax, sc[s]);
        const float m_new = fmaxf(m, tmax);
        const float scale = __expf(m - m_new);    // exp(-inf)=0 on first tile

        if (wrp == 0)    // compute exp once (avoid 256x-redundant MUFU work)
            sp[lane] = (lane < nv) ? __expf(sc[lane] - m_new) : 0.f;

        acc *= scale;
        l   *= scale;
        m    = m_new;
        __syncthreads();

        float lsum = 0.f;
        for (int s = 0; s < nv; s++) {
            const float pv = sp[s];               // broadcast LDS
            lsum += pv;
            acc  += pv * buf[s * DIM + tid];      // conflict-free LDS
        }
        l += lsum;

        __syncthreads();  // protect buf (reused at t+2) and sc/sp before rewrite
    }

    if (tid == 0) { g_m[idx] = m; g_l[idx] = l; }
    g_acc[(size_t)idx * DIM + tid] = acc;
}

// ---------------------------------------------------------------------------
// Kernel 3: merge CHUNKS partials per batch row, normalize, write output.
// grid (BATCH, 4) x 64 threads: block handles dims [64*y, 64*y+64).
// Warp 0 computes merge weights; the dim loop is 32 unconditional, fully
// unrolled coalesced loads (max MLP). Masked chunks: weight=0, g_acc slot=0.
// ---------------------------------------------------------------------------
__global__ __launch_bounds__(64)
void reduce_kernel(float* __restrict__ out) {
    const int b   = blockIdx.x;
    const int d   = blockIdx.y * 64 + threadIdx.x;
    const int tid = threadIdx.x;

    __shared__ float wsh[CHUNKS];
    __shared__ float Lsh;

    if (tid < 32) {
        const float lc = g_l[b * CHUNKS + tid];
        const float mv = g_m[b * CHUNKS + tid];
        float M = (lc > 0.f) ? mv : -CUDART_INF_F;
#pragma unroll
        for (int off = 16; off; off >>= 1)
            M = fmaxf(M, __shfl_xor_sync(0xffffffffu, M, off));
        const float wgt = (lc > 0.f) ? __expf(mv - M) : 0.f;
        float L = lc * wgt;
#pragma unroll
        for (int off = 16; off; off >>= 1)
            L += __shfl_xor_sync(0xffffffffu, L, off);
        wsh[tid] = wgt;
        if (tid == 0) Lsh = L;
    }
    __syncthreads();

    const float* base = g_acc + (size_t)b * CHUNKS * DIM + d;
    float a = 0.f;
#pragma unroll
    for (int ci = 0; ci < CHUNKS; ci++)
        a += wsh[ci] * base[(size_t)ci * DIM];

    out[b * DIM + d] = a / Lsh;
}

// ---------------------------------------------------------------------------
// Launch. Inputs identified by element count (robust to metadata ordering):
//   query 16384 f32, attended 67108864 f32, sequence_lengths 64 (i32 or i64),
//   W 65536 f32, b 256 f32. Output: [B, D] f32.
// ---------------------------------------------------------------------------
extern "C" void kernel_launch(void* const* d_in, const int* in_sizes, int n_in,
                              void* d_out, int out_size) {
    const float* q = nullptr;
    const float* att = nullptr;
    const void*  lens = nullptr;
    const float* W = nullptr;
    const float* bias = nullptr;

    for (int i = 0; i < n_in; i++) {
        switch (in_sizes[i]) {
            case BATCH * DIM:                 q    = (const float*)d_in[i]; break;
            case S_TOTAL * BATCH * DIM:       att  = (const float*)d_in[i]; break;
            case BATCH:                       lens = d_in[i];               break;
            case DIM * DIM:                   W    = (const float*)d_in[i]; break;
            case DIM:                         bias = (const float*)d_in[i]; break;
            default: break;
        }
    }

    float* out = (float*)d_out;

    // dyn smem: 2 tile buffers + keys + sc + sp (66816 B > 48K default).
    // cudaFuncSetAttribute is idempotent; call unconditionally (no static state).
    const int smem_bytes = (2 * SUB_S * DIM + DIM + 2 * SUB_S) * (int)sizeof(float);
    cudaFuncSetAttribute(flash_kernel,
                         cudaFuncAttributeMaxDynamicSharedMemorySize,
                         smem_bytes);

    key_kernel<<<BATCH, DIM>>>(q, W, bias, (const int*)lens);
    dim3 grid(CHUNKS, BATCH);
    flash_kernel<<<grid, DIM, smem_bytes>>>(att, lens);
    dim3 rgrid(BATCH, 4);
    reduce_kernel<<<rgrid, 64>>>(out);
}

// round 9
// speedup vs baseline: 1.4085x; 1.1362x over previous
#include <cuda_runtime.h>
#include <cuda_pipeline.h>
#include <math_constants.h>

#define S_TOTAL 4096
#define BATCH   64
#define DIM     256
#define CHUNKS  32
#define CHUNK_S 128   // S_TOTAL / CHUNKS
#define SUB_S   32    // subtile rows staged per pipeline stage

// Scratch (allocation-free rule: __device__ globals; zero-initialized at load,
// masked chunks' g_acc/g_m/g_l slots are never written -> stay finite 0).
__device__ float g_key[BATCH * DIM];
__device__ float g_m[BATCH * CHUNKS];
__device__ float g_l[BATCH * CHUNKS];
__device__ float g_acc[BATCH * CHUNKS * DIM];
__device__ int   g_len_is64;   // 1 if sequence_lengths is int64, 0 if int32

__device__ __forceinline__ int load_len(const void* lens, int b) {
    if (g_len_is64)
        return (int)((const long long*)lens)[b];
    return ((const int*)lens)[b];
}

// ---------------------------------------------------------------------------
// Kernel 1: key[b][d] = bias[d] + sum_j query[b][j] * W[d][j]
// grid (BATCH, 4), 256 threads. Block (b, y) computes outputs
// d in [y*64, y*64+64): warp w owns d = y*64 + w, w+8, ... (8 outputs/warp).
// Lanes stride over j with two coalesced float4 loads of W row d; the q
// fragment is register-resident (hoisted); shuffle-reduce per output.
// This replaces the old per-thread-row access where adjacent lanes were
// 1KB apart (32 lines per LDG.128 -> L1tex wavefront storm, 14.4us).
// Block (0,0)/thread 0 also detects the sequence_lengths dtype: lengths are
// all >= 1, so viewing the buffer as int32 words, odd words are ALL zero iff
// the layout is int64 (high halves). flash_kernel launches after this kernel
// completes, so the flag write is ordered.
// ---------------------------------------------------------------------------
__global__ __launch_bounds__(DIM)
void key_kernel(const float* __restrict__ q,
                const float* __restrict__ W,
                const float* __restrict__ bias,
                const int*   __restrict__ lens_w) {
    const int b = blockIdx.x;
    const int y = blockIdx.y;
    const int t = threadIdx.x;
    if (b == 0 && y == 0 && t == 0) {
        int any_odd_nonzero = 0;
#pragma unroll
        for (int i = 1; i < 64; i += 2)
            any_odd_nonzero |= (lens_w[i] != 0);
        g_len_is64 = any_odd_nonzero ? 0 : 1;
    }
    __shared__ float qs[DIM];
    qs[t] = q[b * DIM + t];
    __syncthreads();

    const int lane = t & 31;
    const int wrp  = t >> 5;
    const float4* q4 = reinterpret_cast<const float4*>(qs);
    const float4 a0 = q4[lane];        // j = lane*4 .. lane*4+3
    const float4 a1 = q4[lane + 32];   // j = 128 + lane*4 ..

#pragma unroll
    for (int i = 0; i < 8; i++) {
        const int d = y * 64 + wrp + i * 8;
        const float4* W4 = reinterpret_cast<const float4*>(W + (size_t)d * DIM);
        const float4 w0 = W4[lane];
        const float4 w1 = W4[lane + 32];
        float p = w0.x * a0.x + w0.y * a0.y + w0.z * a0.z + w0.w * a0.w
                + w1.x * a1.x + w1.y * a1.y + w1.z * a1.z + w1.w * a1.w;
#pragma unroll
        for (int off = 16; off; off >>= 1)
            p += __shfl_xor_sync(0xffffffffu, p, off);
        if (lane == 0)
            g_key[b * DIM + d] = bias[d] + p;
    }
}

// ---------------------------------------------------------------------------
// Kernel 2: flash-style partial softmax-attention over one (batch, chunk),
// with a 2-stage cp.async pipeline staging 32-row subtiles so DRAM latency
// overlaps compute within the CTA.
// Dynamic SMEM layout: tile[2][SUB_S*DIM] | keys[DIM] | sc[SUB_S] | sp[SUB_S]
// ---------------------------------------------------------------------------
__global__ __launch_bounds__(DIM)
void flash_kernel(const float* __restrict__ attended,
                  const void* __restrict__ lens) {
    const int c   = blockIdx.x;
    const int b   = blockIdx.y;
    const int tid = threadIdx.x;
    const int len = load_len(lens, b);
    const int sbeg = c * CHUNK_S;
    const int idx  = b * CHUNKS + c;

    if (len <= sbeg) {
        if (tid == 0) g_l[idx] = 0.f;   // mark invalid; reducer gives it weight 0
        return;
    }

    extern __shared__ float smem[];
    float* tile = smem;                           // 2 * SUB_S * DIM floats
    float* keys = smem + 2 * SUB_S * DIM;         // DIM
    float* sc   = keys + DIM;                     // SUB_S
    float* sp   = sc + SUB_S;                     // SUB_S

    keys[tid] = g_key[b * DIM + tid];

    const int send = min(sbeg + CHUNK_S, len);
    const int nsub = (send - sbeg + SUB_S - 1) / SUB_S;
    const int lane = tid & 31;
    const int wrp  = tid >> 5;

    const float4* src_base = reinterpret_cast<const float4*>(
        attended + (size_t)b * DIM);

    // issue async stage of subtile t into buffer t&1
    auto issue = [&](int t) {
        const int s0 = sbeg + t * SUB_S;
        const int nv = min(SUB_S, send - s0);
        float4* dst = reinterpret_cast<float4*>(tile + (t & 1) * SUB_S * DIM);
        const float4* src = src_base + (size_t)s0 * (BATCH * DIM / 4);
        for (int i = tid; i < nv * (DIM / 4); i += DIM) {
            int r  = i >> 6;      // / (DIM/4)
            int c4 = i & 63;
            __pipeline_memcpy_async(&dst[r * (DIM / 4) + c4],
                                    &src[(size_t)r * (BATCH * DIM / 4) + c4], 16);
        }
        __pipeline_commit();
    };

    issue(0);

    float m = -CUDART_INF_F;
    float l = 0.f;
    float acc = 0.f;

    for (int t = 0; t < nsub; t++) {
        const int s0 = sbeg + t * SUB_S;
        const int nv = min(SUB_S, send - s0);
        float* buf = tile + (t & 1) * SUB_S * DIM;

        if (t + 1 < nsub) {
            issue(t + 1);
            __pipeline_wait_prior(1);   // group t complete, t+1 in flight
        } else {
            __pipeline_wait_prior(0);
        }
        __syncthreads();                 // staged data visible to all threads

        // --- scores: warp w handles s = w, w+8, ...; stride-32 lane access
        for (int s = wrp; s < nv; s += 8) {
            const float* trow = buf + s * DIM;
            float p = 0.f;
#pragma unroll
            for (int k = 0; k < 8; k++)
                p += trow[lane + 32 * k] * keys[lane + 32 * k];
#pragma unroll
            for (int off = 16; off; off >>= 1)
                p += __shfl_xor_sync(0xffffffffu, p, off);
            if (lane == 0) sc[s] = p;
        }
        __syncthreads();

        // --- online softmax update
        float tmax = -CUDART_INF_F;
        for (int s = 0; s < nv; s++) tmax = fmaxf(tmax, sc[s]);
        const float m_new = fmaxf(m, tmax);
        const float scale = __expf(m - m_new);    // exp(-inf)=0 on first tile

        if (wrp == 0)    // compute exp once (avoid 256x-redundant MUFU work)
            sp[lane] = (lane < nv) ? __expf(sc[lane] - m_new) : 0.f;

        acc *= scale;
        l   *= scale;
        m    = m_new;
        __syncthreads();

        float lsum = 0.f;
        for (int s = 0; s < nv; s++) {
            const float pv = sp[s];               // broadcast LDS
            lsum += pv;
            acc  += pv * buf[s * DIM + tid];      // conflict-free LDS
        }
        l += lsum;

        __syncthreads();  // protect buf (reused at t+2) and sc/sp before rewrite
    }

    if (tid == 0) { g_m[idx] = m; g_l[idx] = l; }
    g_acc[(size_t)idx * DIM + tid] = acc;
}

// ---------------------------------------------------------------------------
// Kernel 3: merge CHUNKS partials per batch row, normalize, write output.
// grid (BATCH, 4) x 64 threads: block handles dims [64*y, 64*y+64).
// Warp 0 computes merge weights; the dim loop is 32 unconditional, fully
// unrolled coalesced loads (max MLP). Masked chunks: weight=0, g_acc slot=0.
// ---------------------------------------------------------------------------
__global__ __launch_bounds__(64)
void reduce_kernel(float* __restrict__ out) {
    const int b   = blockIdx.x;
    const int d   = blockIdx.y * 64 + threadIdx.x;
    const int tid = threadIdx.x;

    __shared__ float wsh[CHUNKS];
    __shared__ float Lsh;

    if (tid < 32) {
        const float lc = g_l[b * CHUNKS + tid];
        const float mv = g_m[b * CHUNKS + tid];
        float M = (lc > 0.f) ? mv : -CUDART_INF_F;
#pragma unroll
        for (int off = 16; off; off >>= 1)
            M = fmaxf(M, __shfl_xor_sync(0xffffffffu, M, off));
        const float wgt = (lc > 0.f) ? __expf(mv - M) : 0.f;
        float L = lc * wgt;
#pragma unroll
        for (int off = 16; off; off >>= 1)
            L += __shfl_xor_sync(0xffffffffu, L, off);
        wsh[tid] = wgt;
        if (tid == 0) Lsh = L;
    }
    __syncthreads();

    const float* base = g_acc + (size_t)b * CHUNKS * DIM + d;
    float a = 0.f;
#pragma unroll
    for (int ci = 0; ci < CHUNKS; ci++)
        a += wsh[ci] * base[(size_t)ci * DIM];

    out[b * DIM + d] = a / Lsh;
}

// ---------------------------------------------------------------------------
// Launch. Inputs identified by element count (robust to metadata ordering):
//   query 16384 f32, attended 67108864 f32, sequence_lengths 64 (i32 or i64),
//   W 65536 f32, b 256 f32. Output: [B, D] f32.
// ---------------------------------------------------------------------------
extern "C" void kernel_launch(void* const* d_in, const int* in_sizes, int n_in,
                              void* d_out, int out_size) {
    const float* q = nullptr;
    const float* att = nullptr;
    const void*  lens = nullptr;
    const float* W = nullptr;
    const float* bias = nullptr;

    for (int i = 0; i < n_in; i++) {
        switch (in_sizes[i]) {
            case BATCH * DIM:                 q    = (const float*)d_in[i]; break;
            case S_TOTAL * BATCH * DIM:       att  = (const float*)d_in[i]; break;
            case BATCH:                       lens = d_in[i];               break;
            case DIM * DIM:                   W    = (const float*)d_in[i]; break;
            case DIM:                         bias = (const float*)d_in[i]; break;
            default: break;
        }
    }

    float* out = (float*)d_out;

    // dyn smem: 2 tile buffers + keys + sc + sp (66816 B > 48K default).
    // cudaFuncSetAttribute is idempotent; call unconditionally (no static state).
    const int smem_bytes = (2 * SUB_S * DIM + DIM + 2 * SUB_S) * (int)sizeof(float);
    cudaFuncSetAttribute(flash_kernel,
                         cudaFuncAttributeMaxDynamicSharedMemorySize,
                         smem_bytes);

    dim3 kgrid(BATCH, 4);
    key_kernel<<<kgrid, DIM>>>(q, W, bias, (const int*)lens);
    dim3 grid(CHUNKS, BATCH);
    flash_kernel<<<grid, DIM, smem_bytes>>>(att, lens);
    dim3 rgrid(BATCH, 4);
    reduce_kernel<<<rgrid, 64>>>(out);
}

// round 10
// speedup vs baseline: 1.4216x; 1.0093x over previous
#include <cuda_runtime.h>
#include <cuda_pipeline.h>
#include <math_constants.h>

#define S_TOTAL 4096
#define BATCH   64
#define DIM     256
#define CHUNKS  32
#define CHUNK_S 128   // S_TOTAL / CHUNKS
#define SUB_S   32    // subtile rows staged per pipeline stage

// Scratch (allocation-free rule: __device__ globals; zero-initialized at load,
// masked chunks' g_acc/g_m/g_l slots are never written -> stay finite 0).
__device__ float g_key[BATCH * DIM];
__device__ float g_m[BATCH * CHUNKS];
__device__ float g_l[BATCH * CHUNKS];
__device__ float g_acc[BATCH * CHUNKS * DIM];
__device__ int   g_len_is64;   // 1 if sequence_lengths is int64, 0 if int32

__device__ __forceinline__ int load_len(const void* lens, int b) {
    if (g_len_is64)
        return (int)((const long long*)lens)[b];
    return ((const int*)lens)[b];
}

// ---------------------------------------------------------------------------
// Kernel 1: key[b][d] = bias[d] + sum_j query[b][j] * W[d][j]
// grid (BATCH, 4), 256 threads. Block (b, y) computes outputs
// d in [y*64, y*64+64): warp w owns d = y*64 + w, w+8, ... (8 outputs/warp).
// Lanes stride over j with two coalesced float4 loads of W row d; the q
// fragment is register-resident (hoisted); shuffle-reduce per output.
// This replaces the old per-thread-row access where adjacent lanes were
// 1KB apart (32 lines per LDG.128 -> L1tex wavefront storm, 14.4us).
// Block (0,0)/thread 0 also detects the sequence_lengths dtype: lengths are
// all >= 1, so viewing the buffer as int32 words, odd words are ALL zero iff
// the layout is int64 (high halves). flash_kernel launches after this kernel
// completes, so the flag write is ordered.
// ---------------------------------------------------------------------------
__global__ __launch_bounds__(DIM)
void key_kernel(const float* __restrict__ q,
                const float* __restrict__ W,
                const float* __restrict__ bias,
                const int*   __restrict__ lens_w) {
    const int b = blockIdx.x;
    const int y = blockIdx.y;
    const int t = threadIdx.x;
    if (b == 0 && y == 0 && t == 0) {
        int any_odd_nonzero = 0;
#pragma unroll
        for (int i = 1; i < 64; i += 2)
            any_odd_nonzero |= (lens_w[i] != 0);
        g_len_is64 = any_odd_nonzero ? 0 : 1;
    }
    __shared__ float qs[DIM];
    qs[t] = q[b * DIM + t];
    __syncthreads();

    const int lane = t & 31;
    const int wrp  = t >> 5;
    const float4* q4 = reinterpret_cast<const float4*>(qs);
    const float4 a0 = q4[lane];        // j = lane*4 .. lane*4+3
    const float4 a1 = q4[lane + 32];   // j = 128 + lane*4 ..

#pragma unroll
    for (int i = 0; i < 8; i++) {
        const int d = y * 64 + wrp + i * 8;
        const float4* W4 = reinterpret_cast<const float4*>(W + (size_t)d * DIM);
        const float4 w0 = W4[lane];
        const float4 w1 = W4[lane + 32];
        float p = w0.x * a0.x + w0.y * a0.y + w0.z * a0.z + w0.w * a0.w
                + w1.x * a1.x + w1.y * a1.y + w1.z * a1.z + w1.w * a1.w;
#pragma unroll
        for (int off = 16; off; off >>= 1)
            p += __shfl_xor_sync(0xffffffffu, p, off);
        if (lane == 0)
            g_key[b * DIM + d] = bias[d] + p;
    }
}

// ---------------------------------------------------------------------------
// Kernel 2: flash-style partial softmax-attention over one (batch, chunk),
// with a 2-stage cp.async pipeline staging 32-row subtiles so DRAM latency
// overlaps compute within the CTA.
// Dynamic SMEM layout: tile[2][SUB_S*DIM] | keys[DIM] | sc[SUB_S] | sp[SUB_S]
// ---------------------------------------------------------------------------
__global__ __launch_bounds__(DIM)
void flash_kernel(const float* __restrict__ attended,
                  const void* __restrict__ lens) {
    const int c   = blockIdx.x;
    const int b   = blockIdx.y;
    const int tid = threadIdx.x;
    const int len = load_len(lens, b);
    const int sbeg = c * CHUNK_S;
    const int idx  = b * CHUNKS + c;

    if (len <= sbeg) {
        if (tid == 0) g_l[idx] = 0.f;   // mark invalid; reducer gives it weight 0
        return;
    }

    extern __shared__ float smem[];
    float* tile = smem;                           // 2 * SUB_S * DIM floats
    float* keys = smem + 2 * SUB_S * DIM;         // DIM
    float* sc   = keys + DIM;                     // SUB_S
    float* sp   = sc + SUB_S;                     // SUB_S

    keys[tid] = g_key[b * DIM + tid];

    const int send = min(sbeg + CHUNK_S, len);
    const int nsub = (send - sbeg + SUB_S - 1) / SUB_S;
    const int lane = tid & 31;
    const int wrp  = tid >> 5;

    const float4* src_base = reinterpret_cast<const float4*>(
        attended + (size_t)b * DIM);

    // issue async stage of subtile t into buffer t&1
    auto issue = [&](int t) {
        const int s0 = sbeg + t * SUB_S;
        const int nv = min(SUB_S, send - s0);
        float4* dst = reinterpret_cast<float4*>(tile + (t & 1) * SUB_S * DIM);
        const float4* src = src_base + (size_t)s0 * (BATCH * DIM / 4);
        for (int i = tid; i < nv * (DIM / 4); i += DIM) {
            int r  = i >> 6;      // / (DIM/4)
            int c4 = i & 63;
            __pipeline_memcpy_async(&dst[r * (DIM / 4) + c4],
                                    &src[(size_t)r * (BATCH * DIM / 4) + c4], 16);
        }
        __pipeline_commit();
    };

    issue(0);

    float m = -CUDART_INF_F;
    float l = 0.f;
    float acc = 0.f;

    for (int t = 0; t < nsub; t++) {
        const int s0 = sbeg + t * SUB_S;
        const int nv = min(SUB_S, send - s0);
        float* buf = tile + (t & 1) * SUB_S * DIM;

        if (t + 1 < nsub) {
            issue(t + 1);
            __pipeline_wait_prior(1);   // group t complete, t+1 in flight
        } else {
            __pipeline_wait_prior(0);
        }
        __syncthreads();                 // staged data visible to all threads

        // --- scores: warp w handles s = w, w+8, ...; stride-32 lane access
        for (int s = wrp; s < nv; s += 8) {
            const float* trow = buf + s * DIM;
            float p = 0.f;
#pragma unroll
            for (int k = 0; k < 8; k++)
                p += trow[lane + 32 * k] * keys[lane + 32 * k];
#pragma unroll
            for (int off = 16; off; off >>= 1)
                p += __shfl_xor_sync(0xffffffffu, p, off);
            if (lane == 0) sc[s] = p;
        }
        __syncthreads();

        // --- online softmax update
        float tmax = -CUDART_INF_F;
        for (int s = 0; s < nv; s++) tmax = fmaxf(tmax, sc[s]);
        const float m_new = fmaxf(m, tmax);
        const float scale = __expf(m - m_new);    // exp(-inf)=0 on first tile

        if (wrp == 0)    // compute exp once (avoid 256x-redundant MUFU work)
            sp[lane] = (lane < nv) ? __expf(sc[lane] - m_new) : 0.f;

        acc *= scale;
        l   *= scale;
        m    = m_new;
        __syncthreads();

        float lsum = 0.f;
        for (int s = 0; s < nv; s++) {
            const float pv = sp[s];               // broadcast LDS
            lsum += pv;
            acc  += pv * buf[s * DIM + tid];      // conflict-free LDS
        }
        l += lsum;

        __syncthreads();  // protect buf (reused at t+2) and sc/sp before rewrite
    }

    if (tid == 0) { g_m[idx] = m; g_l[idx] = l; }
    g_acc[(size_t)idx * DIM + tid] = acc;
}

// ---------------------------------------------------------------------------
// Kernel 3: merge CHUNKS partials per batch row, normalize, write output.
// grid (BATCH, 4) x 64 threads: block handles dims [64*y, 64*y+64).
// Warp 0 computes merge weights; the dim loop is 32 unconditional, fully
// unrolled coalesced loads (max MLP). Masked chunks: weight=0, g_acc slot=0.
// ---------------------------------------------------------------------------
__global__ __launch_bounds__(64)
void reduce_kernel(float* __restrict__ out) {
    const int b   = blockIdx.x;
    const int d   = blockIdx.y * 64 + threadIdx.x;
    const int tid = threadIdx.x;

    __shared__ float wsh[CHUNKS];
    __shared__ float Lsh;

    if (tid < 32) {
        const float lc = g_l[b * CHUNKS + tid];
        const float mv = g_m[b * CHUNKS + tid];
        float M = (lc > 0.f) ? mv : -CUDART_INF_F;
#pragma unroll
        for (int off = 16; off; off >>= 1)
            M = fmaxf(M, __shfl_xor_sync(0xffffffffu, M, off));
        const float wgt = (lc > 0.f) ? __expf(mv - M) : 0.f;
        float L = lc * wgt;
#pragma unroll
        for (int off = 16; off; off >>= 1)
            L += __shfl_xor_sync(0xffffffffu, L, off);
        wsh[tid] = wgt;
        if (tid == 0) Lsh = L;
    }
    __syncthreads();

    const float* base = g_acc + (size_t)b * CHUNKS * DIM + d;
    float a = 0.f;
#pragma unroll
    for (int ci = 0; ci < CHUNKS; ci++)
        a += wsh[ci] * base[(size_t)ci * DIM];

    out[b * DIM + d] = a / Lsh;
}

// ---------------------------------------------------------------------------
// Launch. Inputs identified by element count (robust to metadata ordering):
//   query 16384 f32, attended 67108864 f32, sequence_lengths 64 (i32 or i64),
//   W 65536 f32, b 256 f32. Output: [B, D] f32.
// ---------------------------------------------------------------------------
extern "C" void kernel_launch(void* const* d_in, const int* in_sizes, int n_in,
                              void* d_out, int out_size) {
    const float* q = nullptr;
    const float* att = nullptr;
    const void*  lens = nullptr;
    const float* W = nullptr;
    const float* bias = nullptr;

    for (int i = 0; i < n_in; i++) {
        switch (in_sizes[i]) {
            case BATCH * DIM:                 q    = (const float*)d_in[i]; break;
            case S_TOTAL * BATCH * DIM:       att  = (const float*)d_in[i]; break;
            case BATCH:                       lens = d_in[i];               break;
            case DIM * DIM:                   W    = (const float*)d_in[i]; break;
            case DIM:                         bias = (const float*)d_in[i]; break;
            default: break;
        }
    }

    float* out = (float*)d_out;

    // dyn smem: 2 tile buffers + keys + sc + sp (66816 B > 48K default).
    // cudaFuncSetAttribute is idempotent; call unconditionally (no static state).
    const int smem_bytes = (2 * SUB_S * DIM + DIM + 2 * SUB_S) * (int)sizeof(float);
    cudaFuncSetAttribute(flash_kernel,
                         cudaFuncAttributeMaxDynamicSharedMemorySize,
                         smem_bytes);

    dim3 kgrid(BATCH, 4);
    key_kernel<<<kgrid, DIM>>>(q, W, bias, (const int*)lens);
    dim3 grid(CHUNKS, BATCH);
    flash_kernel<<<grid, DIM, smem_bytes>>>(att, lens);
    dim3 rgrid(BATCH, 4);
    reduce_kernel<<<rgrid, 64>>>(out);
}

// round 11
// speedup vs baseline: 1.4603x; 1.0272x over previous
#include <cuda_runtime.h>
#include <cuda_pipeline.h>
#include <math_constants.h>

#define S_TOTAL 4096
#define BATCH   64
#define DIM     256
#define CHUNKS  32
#define CHUNK_S 128   // S_TOTAL / CHUNKS
#define SUB_S   32    // subtile rows staged per pipeline stage

// Scratch (allocation-free rule: __device__ globals; zero-initialized at load,
// masked chunks' g_acc/g_m/g_l slots are never written -> stay finite 0).
__device__ float g_key[BATCH * DIM];
__device__ float g_m[BATCH * CHUNKS];
__device__ float g_l[BATCH * CHUNKS];
__device__ float g_acc[BATCH * CHUNKS * DIM];
__device__ int   g_len_is64;   // 1 if sequence_lengths is int64, 0 if int32

__device__ __forceinline__ int load_len(const void* lens, int b) {
    if (g_len_is64)
        return (int)((const long long*)lens)[b];
    return ((const int*)lens)[b];
}

// ---------------------------------------------------------------------------
// Kernel 1: key[b][d] = bias[d] + sum_j query[b][j] * W[d][j]
// grid (BATCH, 4), 256 threads. Block (b, y) computes outputs
// d in [y*64, y*64+64): warp w owns d = y*64 + w, w+8, ... (8 outputs/warp).
// Lanes stride over j with two coalesced float4 loads of W row d; the q
// fragment is register-resident (hoisted); shuffle-reduce per output.
// This replaces the old per-thread-row access where adjacent lanes were
// 1KB apart (32 lines per LDG.128 -> L1tex wavefront storm, 14.4us).
// Block (0,0)/thread 0 also detects the sequence_lengths dtype: lengths are
// all >= 1, so viewing the buffer as int32 words, odd words are ALL zero iff
// the layout is int64 (high halves). flash_kernel launches after this kernel
// completes, so the flag write is ordered.
// ---------------------------------------------------------------------------
__global__ __launch_bounds__(DIM)
void key_kernel(const float* __restrict__ q,
                const float* __restrict__ W,
                const float* __restrict__ bias,
                const int*   __restrict__ lens_w) {
    const int b = blockIdx.x;
    const int y = blockIdx.y;
    const int t = threadIdx.x;
    if (b == 0 && y == 0 && t == 0) {
        int any_odd_nonzero = 0;
#pragma unroll
        for (int i = 1; i < 64; i += 2)
            any_odd_nonzero |= (lens_w[i] != 0);
        g_len_is64 = any_odd_nonzero ? 0 : 1;
    }
    __shared__ float qs[DIM];
    qs[t] = q[b * DIM + t];
    __syncthreads();

    const int lane = t & 31;
    const int wrp  = t >> 5;
    const float4* q4 = reinterpret_cast<const float4*>(qs);
    const float4 a0 = q4[lane];        // j = lane*4 .. lane*4+3
    const float4 a1 = q4[lane + 32];   // j = 128 + lane*4 ..

#pragma unroll
    for (int i = 0; i < 8; i++) {
        const int d = y * 64 + wrp + i * 8;
        const float4* W4 = reinterpret_cast<const float4*>(W + (size_t)d * DIM);
        const float4 w0 = W4[lane];
        const float4 w1 = W4[lane + 32];
        float p = w0.x * a0.x + w0.y * a0.y + w0.z * a0.z + w0.w * a0.w
                + w1.x * a1.x + w1.y * a1.y + w1.z * a1.z + w1.w * a1.w;
#pragma unroll
        for (int off = 16; off; off >>= 1)
            p += __shfl_xor_sync(0xffffffffu, p, off);
        if (lane == 0)
            g_key[b * DIM + d] = bias[d] + p;
    }
}

// ---------------------------------------------------------------------------
// Kernel 2: flash-style partial softmax-attention over one (batch, chunk),
// with a 2-stage cp.async pipeline staging 32-row subtiles so DRAM latency
// overlaps compute within the CTA.
// Dynamic SMEM layout: tile[2][SUB_S*DIM] | keys[DIM] | sc[SUB_S] | sp[SUB_S]
// ---------------------------------------------------------------------------
__global__ __launch_bounds__(DIM)
void flash_kernel(const float* __restrict__ attended,
                  const void* __restrict__ lens) {
    const int c   = blockIdx.x;
    const int b   = blockIdx.y;
    const int tid = threadIdx.x;
    const int len = load_len(lens, b);
    const int sbeg = c * CHUNK_S;
    const int idx  = b * CHUNKS + c;

    if (len <= sbeg) {
        if (tid == 0) g_l[idx] = 0.f;   // mark invalid; reducer gives it weight 0
        return;
    }

    extern __shared__ float smem[];
    float* tile = smem;                           // 2 * SUB_S * DIM floats
    float* keys = smem + 2 * SUB_S * DIM;         // DIM
    float* sc   = keys + DIM;                     // SUB_S
    float* sp   = sc + SUB_S;                     // SUB_S

    keys[tid] = g_key[b * DIM + tid];

    const int send = min(sbeg + CHUNK_S, len);
    const int nsub = (send - sbeg + SUB_S - 1) / SUB_S;
    const int lane = tid & 31;
    const int wrp  = tid >> 5;

    const float4* src_base = reinterpret_cast<const float4*>(
        attended + (size_t)b * DIM);

    // issue async stage of subtile t into buffer t&1
    auto issue = [&](int t) {
        const int s0 = sbeg + t * SUB_S;
        const int nv = min(SUB_S, send - s0);
        float4* dst = reinterpret_cast<float4*>(tile + (t & 1) * SUB_S * DIM);
        const float4* src = src_base + (size_t)s0 * (BATCH * DIM / 4);
        for (int i = tid; i < nv * (DIM / 4); i += DIM) {
            int r  = i >> 6;      // / (DIM/4)
            int c4 = i & 63;
            __pipeline_memcpy_async(&dst[r * (DIM / 4) + c4],
                                    &src[(size_t)r * (BATCH * DIM / 4) + c4], 16);
        }
        __pipeline_commit();
    };

    issue(0);

    float m = -CUDART_INF_F;
    float l = 0.f;
    float acc = 0.f;

    for (int t = 0; t < nsub; t++) {
        const int s0 = sbeg + t * SUB_S;
        const int nv = min(SUB_S, send - s0);
        float* buf = tile + (t & 1) * SUB_S * DIM;

        if (t + 1 < nsub) {
            issue(t + 1);
            __pipeline_wait_prior(1);   // group t complete, t+1 in flight
        } else {
            __pipeline_wait_prior(0);
        }
        __syncthreads();                 // staged data visible to all threads

        // --- scores: warp w handles s = w, w+8, ...; stride-32 lane access
        for (int s = wrp; s < nv; s += 8) {
            const float* trow = buf + s * DIM;
            float p = 0.f;
#pragma unroll
            for (int k = 0; k < 8; k++)
                p += trow[lane + 32 * k] * keys[lane + 32 * k];
#pragma unroll
            for (int off = 16; off; off >>= 1)
                p += __shfl_xor_sync(0xffffffffu, p, off);
            if (lane == 0) sc[s] = p;
        }
        __syncthreads();

        // --- online softmax update
        float tmax = -CUDART_INF_F;
        for (int s = 0; s < nv; s++) tmax = fmaxf(tmax, sc[s]);
        const float m_new = fmaxf(m, tmax);
        const float scale = __expf(m - m_new);    // exp(-inf)=0 on first tile

        if (wrp == 0)    // compute exp once (avoid 256x-redundant MUFU work)
            sp[lane] = (lane < nv) ? __expf(sc[lane] - m_new) : 0.f;

        acc *= scale;
        l   *= scale;
        m    = m_new;
        __syncthreads();

        float lsum = 0.f;
        for (int s = 0; s < nv; s++) {
            const float pv = sp[s];               // broadcast LDS
            lsum += pv;
            acc  += pv * buf[s * DIM + tid];      // conflict-free LDS
        }
        l += lsum;

        __syncthreads();  // protect buf (reused at t+2) and sc/sp before rewrite
    }

    if (tid == 0) { g_m[idx] = m; g_l[idx] = l; }
    g_acc[(size_t)idx * DIM + tid] = acc;
}

// ---------------------------------------------------------------------------
// Kernel 3: merge CHUNKS partials per batch row, normalize, write output.
// grid (BATCH, 4) x 64 threads: block handles dims [64*y, 64*y+64).
// Warp 0 computes merge weights; the dim loop is 32 unconditional, fully
// unrolled coalesced loads (max MLP). Masked chunks: weight=0, g_acc slot=0.
// ---------------------------------------------------------------------------
__global__ __launch_bounds__(64)
void reduce_kernel(float* __restrict__ out) {
    const int b   = blockIdx.x;
    const int d   = blockIdx.y * 64 + threadIdx.x;
    const int tid = threadIdx.x;

    __shared__ float wsh[CHUNKS];
    __shared__ float Lsh;

    if (tid < 32) {
        const float lc = g_l[b * CHUNKS + tid];
        const float mv = g_m[b * CHUNKS + tid];
        float M = (lc > 0.f) ? mv : -CUDART_INF_F;
#pragma unroll
        for (int off = 16; off; off >>= 1)
            M = fmaxf(M, __shfl_xor_sync(0xffffffffu, M, off));
        const float wgt = (lc > 0.f) ? __expf(mv - M) : 0.f;
        float L = lc * wgt;
#pragma unroll
        for (int off = 16; off; off >>= 1)
            L += __shfl_xor_sync(0xffffffffu, L, off);
        wsh[tid] = wgt;
        if (tid == 0) Lsh = L;
    }
    __syncthreads();

    const float* base = g_acc + (size_t)b * CHUNKS * DIM + d;
    float a = 0.f;
#pragma unroll
    for (int ci = 0; ci < CHUNKS; ci++)
        a += wsh[ci] * base[(size_t)ci * DIM];

    out[b * DIM + d] = a / Lsh;
}

// ---------------------------------------------------------------------------
// Launch. Inputs identified by element count (robust to metadata ordering):
//   query 16384 f32, attended 67108864 f32, sequence_lengths 64 (i32 or i64),
//   W 65536 f32, b 256 f32. Output: [B, D] f32.
// ---------------------------------------------------------------------------
extern "C" void kernel_launch(void* const* d_in, const int* in_sizes, int n_in,
                              void* d_out, int out_size) {
    const float* q = nullptr;
    const float* att = nullptr;
    const void*  lens = nullptr;
    const float* W = nullptr;
    const float* bias = nullptr;

    for (int i = 0; i < n_in; i++) {
        switch (in_sizes[i]) {
            case BATCH * DIM:                 q    = (const float*)d_in[i]; break;
            case S_TOTAL * BATCH * DIM:       att  = (const float*)d_in[i]; break;
            case BATCH:                       lens = d_in[i];               break;
            case DIM * DIM:                   W    = (const float*)d_in[i]; break;
            case DIM:                         bias = (const float*)d_in[i]; break;
            default: break;
        }
    }

    float* out = (float*)d_out;

    // dyn smem: 2 tile buffers + keys + sc + sp (66816 B > 48K default).
    // cudaFuncSetAttribute is idempotent; call unconditionally (no static state).
    const int smem_bytes = (2 * SUB_S * DIM + DIM + 2 * SUB_S) * (int)sizeof(float);
    cudaFuncSetAttribute(flash_kernel,
                         cudaFuncAttributeMaxDynamicSharedMemorySize,
                         smem_bytes);

    dim3 kgrid(BATCH, 4);
    key_kernel<<<kgrid, DIM>>>(q, W, bias, (const int*)lens);
    dim3 grid(CHUNKS, BATCH);
    flash_kernel<<<grid, DIM, smem_bytes>>>(att, lens);
    dim3 rgrid(BATCH, 4);
    reduce_kernel<<<rgrid, 64>>>(out);
}